// round 3
// baseline (speedup 1.0000x reference)
#include <cuda_runtime.h>
#include <math.h>
#include <float.h>

// Problem constants (fixed by the dataset)
#define BB   256      // batch
#define CC   128      // embedding dim C
#define KK   4096     // negatives per sample
#define NCLSS 100     // n classes
#define KNNK 8
#define INV_T 14.285714285714286f   // 1/0.07
#define LSE_SHIFT 25.0f             // hard bound: |dot|<=1.733 -> /T <= 24.8

// ---------------- scratch (device globals; no allocation allowed) ----------
__device__ __align__(16) float g_fes[BB*CC];
__device__ __align__(16) float g_fet[BB*CC];
__device__ __align__(16) float g_fgs[BB*CC];
__device__ __align__(16) float g_fgt[BB*CC];
__device__ __align__(16) float g_u[2*BB*NCLSS];   // normalized softmax rows
__device__ int   g_nbr[2*BB*KNNK];
__device__ float g_pos[4*BB];          // 0:ls 1:lt 2:gs 3:gt
__device__ float g_psum[4][BB][2];     // partial exp-sums per stream, per b, per k-half

// ---------------- embed: f_e = l2norm(x @ W^T + b) --------------------------
template<int D, int ROWS>
__global__ __launch_bounds__(128) void embed_kernel(const float* __restrict__ x,
        const float* __restrict__ W, const float* __restrict__ bias)
{
    __shared__ float xs[ROWS*D];
    __shared__ float red[CC];
    float* out = (D == 1024) ? g_fes : g_fet;
    const int c = threadIdx.x;
    const int g = blockIdx.x;
    const float* xrow = x + (size_t)g*ROWS*D;
    for (int t = c; t < ROWS*D; t += 128) xs[t] = xrow[t];
    __syncthreads();

    float acc[ROWS];
    #pragma unroll
    for (int r = 0; r < ROWS; r++) acc[r] = 0.f;

    const float4* w4 = (const float4*)(W + (size_t)c*D);
    #pragma unroll 4
    for (int i = 0; i < D/4; i++) {
        float4 w = w4[i];
        #pragma unroll
        for (int r = 0; r < ROWS; r++) {
            float4 xv = ((const float4*)(xs + r*D))[i];
            acc[r] += w.x*xv.x + w.y*xv.y + w.z*xv.z + w.w*xv.w;
        }
    }
    float bv = bias[c];
    #pragma unroll
    for (int r = 0; r < ROWS; r++) acc[r] += bv;

    for (int r = 0; r < ROWS; r++) {
        red[c] = acc[r]*acc[r];
        __syncthreads();
        for (int off = 64; off > 0; off >>= 1) {
            if (c < off) red[c] += red[c+off];
            __syncthreads();
        }
        float inv = rsqrtf(red[0]);
        __syncthreads();
        out[(size_t)(g*ROWS + r)*CC + c] = acc[r]*inv;
    }
}

// ---------------- softmax rows, normalized: u = e / ||e|| -------------------
__global__ __launch_bounds__(128) void soft_kernel(const float* __restrict__ ls,
                                                   const float* __restrict__ lt)
{
    const int b = blockIdx.x, which = blockIdx.y;
    const float* l = (which ? lt : ls) + (size_t)b*NCLSS;
    float* u = g_u + ((size_t)which*BB + b)*NCLSS;
    const int t = threadIdx.x;
    __shared__ float red[128];

    float v = (t < NCLSS) ? l[t] : -FLT_MAX;
    red[t] = v; __syncthreads();
    for (int off = 64; off > 0; off >>= 1) { if (t < off) red[t] = fmaxf(red[t], red[t+off]); __syncthreads(); }
    float mx = red[0]; __syncthreads();

    float e = (t < NCLSS) ? expf(v - mx) : 0.f;
    red[t] = e*e; __syncthreads();
    for (int off = 64; off > 0; off >>= 1) { if (t < off) red[t] += red[t+off]; __syncthreads(); }
    float inv = rsqrtf(red[0]);
    if (t < NCLSS) u[t] = e*inv;
}

// ---------------- knn: top-8 of (-dist), warp-register selection ------------
// dot via float4 + 4 accumulators (100 floats = 25 float4; 25 = 6*4+1)
__global__ __launch_bounds__(128) void knn_kernel()
{
    const int i = blockIdx.x, which = blockIdx.y;
    const float* u = g_u + (size_t)which*BB*NCLSS;
    const int t = threadIdx.x, lane = t & 31;
    __shared__ __align__(16) float ui[NCLSS];
    __shared__ float val[BB];

    if (t < NCLSS) ui[t] = u[(size_t)i*NCLSS + t];
    __syncthreads();

    #pragma unroll
    for (int p = 0; p < 2; p++) {
        int jj = t + 128*p;
        const float4* uj4 = (const float4*)(u + (size_t)jj*NCLSS);
        const float4* ui4 = (const float4*)ui;
        float d0 = 0.f, d1 = 0.f, d2 = 0.f, d3 = 0.f;
        #pragma unroll
        for (int e = 0; e < 24; e += 4) {
            float4 a0 = ui4[e+0], b0 = uj4[e+0];
            float4 a1v = ui4[e+1], b1 = uj4[e+1];
            float4 a2v = ui4[e+2], b2 = uj4[e+2];
            float4 a3v = ui4[e+3], b3 = uj4[e+3];
            d0 += a0.x*b0.x + a0.y*b0.y + a0.z*b0.z + a0.w*b0.w;
            d1 += a1v.x*b1.x + a1v.y*b1.y + a1v.z*b1.z + a1v.w*b1.w;
            d2 += a2v.x*b2.x + a2v.y*b2.y + a2v.z*b2.z + a2v.w*b2.w;
            d3 += a3v.x*b3.x + a3v.y*b3.y + a3v.z*b3.z + a3v.w*b3.w;
        }
        { float4 a = ui4[24], b4 = uj4[24];
          d0 += a.x*b4.x + a.y*b4.y + a.z*b4.z + a.w*b4.w; }
        float d = (d0 + d1) + (d2 + d3);
        val[jj] = (jj == i) ? 1.0f : (d - 1.0f);  // = -dist
    }
    __syncthreads();

    if (t < 32) {
        float v[8];
        #pragma unroll
        for (int q = 0; q < 8; q++) v[q] = val[lane + 32*q];

        for (int r = 0; r < KNNK; r++) {
            float bv = v[0]; int bq = 0;
            #pragma unroll
            for (int q = 1; q < 8; q++) if (v[q] > bv) { bv = v[q]; bq = q; }
            int bidx = lane + 32*bq;
            #pragma unroll
            for (int o = 16; o; o >>= 1) {
                float ov = __shfl_xor_sync(0xffffffffu, bv, o);
                int   oi = __shfl_xor_sync(0xffffffffu, bidx, o);
                if (ov > bv || (ov == bv && oi < bidx)) { bv = ov; bidx = oi; }
            }
            if (lane == 0) g_nbr[((size_t)which*BB + i)*KNNK + r] = bidx;
            if (lane == (bidx & 31)) v[bidx >> 5] = -FLT_MAX;
        }
    }
}

// ---------------- gnn_encode: 4 batch rows per CTA --------------------------
__global__ __launch_bounds__(128) void gnn_kernel(const float* __restrict__ Wgs, const float* __restrict__ bgs,
                                                  const float* __restrict__ Wgt, const float* __restrict__ bgt)
{
    const int g = blockIdx.x, which = blockIdx.y;   // g in [0,64)
    const float* fe  = which ? g_fet : g_fes;
    const float* W   = which ? Wgt : Wgs;
    const float* bias= which ? bgt : bgs;
    float* fg        = which ? g_fgt : g_fgs;
    const int c = threadIdx.x;
    __shared__ float h2[4][2*CC];
    __shared__ float red[CC];
    __shared__ int nb[4][KNNK];

    if (c < 32) {
        int rr = c >> 3, q = c & 7;
        nb[rr][q] = g_nbr[((size_t)which*BB + g*4 + rr)*KNNK + q];
    }
    __syncthreads();

    #pragma unroll
    for (int rr = 0; rr < 4; rr++) {
        h2[rr][c] = fe[(size_t)(g*4 + rr)*CC + c];
        float agg = 0.f;
        #pragma unroll
        for (int q = 0; q < KNNK; q++) agg += fe[(size_t)nb[rr][q]*CC + c];
        h2[rr][CC + c] = agg * (1.0f/KNNK);
    }
    __syncthreads();

    float acc[4];
    float bv = bias[c];
    #pragma unroll
    for (int rr = 0; rr < 4; rr++) acc[rr] = bv;
    #pragma unroll 4
    for (int r = 0; r < 2*CC; r++) {
        float wv = W[(size_t)r*CC + c];
        #pragma unroll
        for (int rr = 0; rr < 4; rr++) acc[rr] += h2[rr][r]*wv;
    }

    for (int rr = 0; rr < 4; rr++) {
        red[c] = acc[rr]*acc[rr]; __syncthreads();
        for (int off = 64; off > 0; off >>= 1) { if (c < off) red[c] += red[c+off]; __syncthreads(); }
        float inv = rsqrtf(red[0]); __syncthreads();
        fg[(size_t)(g*4 + rr)*CC + c] = acc[rr]*inv;
    }
}

// ---------------- smooth + positive logits ---------------------------------
__device__ __forceinline__ float breduce128(float v, float* red, int c)
{
    red[c] = v; __syncthreads();
    for (int off = 64; off > 0; off >>= 1) { if (c < off) red[c] += red[c+off]; __syncthreads(); }
    float r = red[0]; __syncthreads();
    return r;
}

__global__ __launch_bounds__(128) void smooth_pos_kernel(const int* __restrict__ idx,
        const float* __restrict__ mem_l, const float* __restrict__ mem_ab)
{
    const int b = blockIdx.x, c = threadIdx.x;
    __shared__ float red[CC];
    const int id = idx[b];
    float ml  = mem_l [(size_t)id*CC + c];
    float mab = mem_ab[(size_t)id*CC + c];
    float fes = g_fes[(size_t)b*CC + c], fet = g_fet[(size_t)b*CC + c];
    float fgs = g_fgs[(size_t)b*CC + c], fgt = g_fgt[(size_t)b*CC + c];

    float sgs = ml *0.75f + fgs*0.25f;
    float sgt = mab*0.75f + fgt*0.25f;
    sgs *= rsqrtf(breduce128(sgs*sgs, red, c));
    sgt *= rsqrtf(breduce128(sgt*sgt, red, c));

    float ls = breduce128(mab*fes, red, c);
    float lt = breduce128(ml *fet, red, c);
    float gs = breduce128(sgt*fgs, red, c);
    float gt = breduce128(sgs*fgt, red, c);
    if (c == 0) {
        g_pos[0*BB+b] = ls; g_pos[1*BB+b] = lt;
        g_pos[2*BB+b] = gs; g_pos[3*BB+b] = gt;
    }
}

// ---------------- heavy kernel: ONE BANK per launch (L2-resident) -----------
// grid 2*BB CTAs: b = blockIdx.x>>1, half = blockIdx.x&1. 256 threads.
// 8 lanes per row, 4 rows per warp iteration; each warp handles 256 indices.
__global__ __launch_bounds__(256, 3) void neg_kernel(const int* __restrict__ cidx,
        const float* __restrict__ mem, int bank)
{
    const int b = blockIdx.x >> 1, half = blockIdx.x & 1;
    const float* v1p = (bank ? g_fet : g_fes) + (size_t)b*CC;
    const float* v2p = (bank ? g_fgt : g_fgs) + (size_t)b*CC;
    const int t = threadIdx.x, w = t >> 5, lane = t & 31;
    const int j = lane & 7;     // segment within row (16 floats each)
    const int r = lane >> 3;    // row within group of 4

    float4 a1[4], a2[4];
    #pragma unroll
    for (int i = 0; i < 4; i++) {
        a1[i] = ((const float4*)v1p)[j + 8*i];
        a2[i] = ((const float4*)v2p)[j + 8*i];
    }

    // this warp's 256 indices
    const int* ci = cidx + (size_t)b*KK + half*(KK/2) + w*(KK/16);

    float s1 = 0.f, s2 = 0.f;
    #pragma unroll 4
    for (int it = 0; it < 64; it++) {
        int row = ci[it*4 + r];                     // 8-way broadcast within group
        const float4* mp = (const float4*)(mem + (size_t)row*CC);
        float d1 = 0.f, d2 = 0.f;
        #pragma unroll
        for (int i = 0; i < 4; i++) {
            float4 x = mp[j + 8*i];
            d1 += x.x*a1[i].x + x.y*a1[i].y + x.z*a1[i].z + x.w*a1[i].w;
            d2 += x.x*a2[i].x + x.y*a2[i].y + x.z*a2[i].z + x.w*a2[i].w;
        }
        #pragma unroll
        for (int o = 4; o; o >>= 1) {
            d1 += __shfl_xor_sync(0xffffffffu, d1, o);
            d2 += __shfl_xor_sync(0xffffffffu, d2, o);
        }
        s1 += __expf(fmaf(d1, INV_T, -LSE_SHIFT));
        s2 += __expf(fmaf(d2, INV_T, -LSE_SHIFT));
    }
    // warp total: 8 identical copies per group -> scale by 1/8 (exact)
    #pragma unroll
    for (int o = 16; o; o >>= 1) {
        s1 += __shfl_xor_sync(0xffffffffu, s1, o);
        s2 += __shfl_xor_sync(0xffffffffu, s2, o);
    }

    __shared__ float ss1[8], ss2[8];
    if (lane == 0) { ss1[w] = s1 * 0.125f; ss2[w] = s2 * 0.125f; }
    __syncthreads();
    if (t == 0) {
        float S1 = 0.f, S2 = 0.f;
        #pragma unroll
        for (int q = 0; q < 8; q++) { S1 += ss1[q]; S2 += ss2[q]; }
        g_psum[bank][b][half]     = S1;   // streams 0(ls)/1(lt)
        g_psum[2 + bank][b][half] = S2;   // streams 2(gs)/3(gt)
    }
}

// ---------------- final reduce ----------------------------------------------
__global__ __launch_bounds__(256) void final_kernel(float* __restrict__ out)
{
    const int t = threadIdx.x;
    __shared__ float red[256];
    float v = 0.f;
    #pragma unroll
    for (int s = 0; s < 4; s++) {
        float p = g_pos[s*BB + t] * INV_T;
        float S = __expf(p - LSE_SHIFT) + g_psum[s][t][0] + g_psum[s][t][1];
        v += LSE_SHIFT + logf(S) - p;
    }
    red[t] = v; __syncthreads();
    for (int off = 128; off > 0; off >>= 1) { if (t < off) red[t] += red[t+off]; __syncthreads(); }
    if (t == 0) out[0] = red[0] * (1.0f/BB);
}

// ---------------- launch -----------------------------------------------------
extern "C" void kernel_launch(void* const* d_in, const int* in_sizes, int n_in,
                              void* d_out, int out_size)
{
    const float* f_s   = (const float*)d_in[1];
    const float* l_s   = (const float*)d_in[2];
    const float* f_t   = (const float*)d_in[3];
    const float* l_t   = (const float*)d_in[4];
    const int*   idx   = (const int*)  d_in[5];
    const int*   cidx  = (const int*)  d_in[6];
    const float* W_es  = (const float*)d_in[7];
    const float* b_es  = (const float*)d_in[8];
    const float* W_et  = (const float*)d_in[9];
    const float* b_et  = (const float*)d_in[10];
    const float* W_gs  = (const float*)d_in[11];
    const float* b_gs  = (const float*)d_in[12];
    const float* W_gt  = (const float*)d_in[13];
    const float* b_gt  = (const float*)d_in[14];
    const float* mem_l = (const float*)d_in[15];
    const float* mem_ab= (const float*)d_in[16];
    float* out = (float*)d_out;

    embed_kernel<1024, 8><<<BB/8, 128>>>(f_s, W_es, b_es);      // -> g_fes
    embed_kernel<2048, 4><<<BB/4, 128>>>(f_t, W_et, b_et);      // -> g_fet
    soft_kernel<<<dim3(BB, 2), 128>>>(l_s, l_t);                // -> g_u
    knn_kernel<<<dim3(BB, 2), 128>>>();                         // -> g_nbr
    gnn_kernel<<<dim3(BB/4, 2), 128>>>(W_gs, b_gs, W_gt, b_gt); // -> g_fgs/g_fgt
    smooth_pos_kernel<<<BB, 128>>>(idx, mem_l, mem_ab);         // -> g_pos
    neg_kernel<<<2*BB, 256>>>(cidx, mem_l, 0);                  // bank 0 (L2-resident)
    neg_kernel<<<2*BB, 256>>>(cidx, mem_ab, 1);                 // bank 1 (L2-resident)
    final_kernel<<<1, 256>>>(out);
}

// round 4
// speedup vs baseline: 1.5706x; 1.5706x over previous
#include <cuda_runtime.h>
#include <math.h>
#include <float.h>

#define BB   256
#define CC   128
#define KK   4096
#define NCLSS 100
#define KNNK 8
#define INV_T 14.285714285714286f   // 1/0.07
#define LSE_SHIFT 25.0f             // |dot| <= 1.733 -> |dot|/T <= 24.8

// ---------------- scratch ----------------------------------------------------
__device__ __align__(16) float g_fes[BB*CC];
__device__ __align__(16) float g_fet[BB*CC];
__device__ __align__(16) float g_fgs[BB*CC];
__device__ __align__(16) float g_fgt[BB*CC];
__device__ __align__(16) float g_u [2*BB*NCLSS];   // row-major normalized softmax
__device__ __align__(16) float g_uT[2*NCLSS*BB];   // transposed copy (for knn)
__device__ int   g_nbr[2*BB*KNNK];
__device__ float g_pos[4*BB];          // 0:ls 1:lt 2:gs 3:gt
__device__ float g_psum[4][BB][4];     // partial exp-sums per stream, b, k-quarter

// ---------------- embed: f_e = l2norm(x @ W^T + b) ---------------------------
// 256 threads, 8 warps. Warp w computes channels [16w, 16w+16) for ROWS rows.
// W reads are lane-strided -> coalesced (4 wavefronts per LDG.128).
template<int D, int ROWS>
__global__ __launch_bounds__(256) void embed_kernel(const float* __restrict__ x,
        const float* __restrict__ W, const float* __restrict__ bias)
{
    __shared__ __align__(16) float xs[ROWS*D];
    __shared__ float outv[CC][ROWS];
    __shared__ float sinv[ROWS];
    float* out = (D == 1024) ? g_fes : g_fet;
    const int t = threadIdx.x, w = t >> 5, lane = t & 31;
    const int g = blockIdx.x;

    const float* xrow = x + (size_t)g*ROWS*D;
    for (int i = t; i < ROWS*D; i += 256) xs[i] = xrow[i];
    __syncthreads();

    const float4* xs4 = (const float4*)xs;
    const float4* W4  = (const float4*)W;
    const int NJ = D/128;   // 128-float chunks

    float acc[16][ROWS];
    #pragma unroll
    for (int cc = 0; cc < 16; cc++)
        #pragma unroll
        for (int r = 0; r < ROWS; r++) acc[cc][r] = 0.f;

    for (int j = 0; j < NJ; j++) {
        float4 xv[ROWS];
        #pragma unroll
        for (int r = 0; r < ROWS; r++) xv[r] = xs4[r*(D/4) + j*32 + lane];
        #pragma unroll
        for (int cc = 0; cc < 16; cc++) {
            const int c = w*16 + cc;
            float4 wv = W4[(size_t)c*(D/4) + j*32 + lane];
            #pragma unroll
            for (int r = 0; r < ROWS; r++)
                acc[cc][r] += wv.x*xv[r].x + wv.y*xv[r].y + wv.z*xv[r].z + wv.w*xv[r].w;
        }
    }

    #pragma unroll
    for (int cc = 0; cc < 16; cc++) {
        const int c = w*16 + cc;
        #pragma unroll
        for (int r = 0; r < ROWS; r++) {
            float v = acc[cc][r];
            #pragma unroll
            for (int o = 16; o; o >>= 1) v += __shfl_xor_sync(0xffffffffu, v, o);
            if (lane == 0) outv[c][r] = v + bias[c];
        }
    }
    __syncthreads();

    if (w < ROWS) {   // warp r computes inverse norm of row r
        float s = 0.f;
        #pragma unroll
        for (int kq = 0; kq < CC/32; kq++) {
            float v = outv[lane + 32*kq][w];
            s += v*v;
        }
        #pragma unroll
        for (int o = 16; o; o >>= 1) s += __shfl_xor_sync(0xffffffffu, s, o);
        if (lane == 0) sinv[w] = rsqrtf(s);
    }
    __syncthreads();

    if (t < CC) {
        #pragma unroll
        for (int r = 0; r < ROWS; r++)
            out[(size_t)(g*ROWS + r)*CC + t] = outv[t][r]*sinv[r];
    }
}

// ---------------- softmax rows, normalized; writes u and uT ------------------
__global__ __launch_bounds__(128) void soft_kernel(const float* __restrict__ ls,
                                                   const float* __restrict__ lt)
{
    const int b = blockIdx.x, which = blockIdx.y;
    const float* l = (which ? lt : ls) + (size_t)b*NCLSS;
    float* u  = g_u  + ((size_t)which*BB + b)*NCLSS;
    const int t = threadIdx.x;
    __shared__ float red[128];

    float v = (t < NCLSS) ? l[t] : -FLT_MAX;
    red[t] = v; __syncthreads();
    for (int off = 64; off > 0; off >>= 1) { if (t < off) red[t] = fmaxf(red[t], red[t+off]); __syncthreads(); }
    float mx = red[0]; __syncthreads();

    float e = (t < NCLSS) ? expf(v - mx) : 0.f;
    red[t] = e*e; __syncthreads();
    for (int off = 64; off > 0; off >>= 1) { if (t < off) red[t] += red[t+off]; __syncthreads(); }
    float inv = rsqrtf(red[0]);
    if (t < NCLSS) {
        float uv = e*inv;
        u[t] = uv;
        g_uT[((size_t)which*NCLSS + t)*BB + b] = uv;
    }
}

// ---------------- knn: top-8 of (-dist), coalesced via uT --------------------
__global__ __launch_bounds__(128) void knn_kernel()
{
    const int i = blockIdx.x, which = blockIdx.y;
    const float* uT = g_uT + (size_t)which*NCLSS*BB;
    const int t = threadIdx.x, lane = t & 31;
    __shared__ float ui[NCLSS];
    __shared__ float val[BB];

    if (t < NCLSS) ui[t] = g_u[((size_t)which*BB + i)*NCLSS + t];
    __syncthreads();

    {
        float v0 = 0.f, v1 = 0.f;
        #pragma unroll 4
        for (int e = 0; e < NCLSS; e++) {
            float uu = ui[e];
            v0 += uu * uT[(size_t)e*BB + t];
            v1 += uu * uT[(size_t)e*BB + t + 128];
        }
        val[t]       = (t       == i) ? 1.0f : (v0 - 1.0f);
        val[t + 128] = (t + 128 == i) ? 1.0f : (v1 - 1.0f);
    }
    __syncthreads();

    if (t < 32) {
        float v[8];
        #pragma unroll
        for (int q = 0; q < 8; q++) v[q] = val[lane + 32*q];

        for (int r = 0; r < KNNK; r++) {
            float bv = v[0]; int bq = 0;
            #pragma unroll
            for (int q = 1; q < 8; q++) if (v[q] > bv) { bv = v[q]; bq = q; }
            int bidx = lane + 32*bq;
            #pragma unroll
            for (int o = 16; o; o >>= 1) {
                float ov = __shfl_xor_sync(0xffffffffu, bv, o);
                int   oi = __shfl_xor_sync(0xffffffffu, bidx, o);
                if (ov > bv || (ov == bv && oi < bidx)) { bv = ov; bidx = oi; }
            }
            if (lane == 0) g_nbr[((size_t)which*BB + i)*KNNK + r] = bidx;
            if (lane == (bidx & 31)) v[bidx >> 5] = -FLT_MAX;
        }
    }
}

// ---------------- gnn_encode: 4 batch rows per CTA ---------------------------
__global__ __launch_bounds__(128) void gnn_kernel(const float* __restrict__ Wgs, const float* __restrict__ bgs,
                                                  const float* __restrict__ Wgt, const float* __restrict__ bgt)
{
    const int g = blockIdx.x, which = blockIdx.y;
    const float* fe  = which ? g_fet : g_fes;
    const float* W   = which ? Wgt : Wgs;
    const float* bias= which ? bgt : bgs;
    float* fg        = which ? g_fgt : g_fgs;
    const int c = threadIdx.x;
    __shared__ float h2[4][2*CC];
    __shared__ float red[CC];
    __shared__ int nb[4][KNNK];

    if (c < 32) {
        int rr = c >> 3, q = c & 7;
        nb[rr][q] = g_nbr[((size_t)which*BB + g*4 + rr)*KNNK + q];
    }
    __syncthreads();

    #pragma unroll
    for (int rr = 0; rr < 4; rr++) {
        h2[rr][c] = fe[(size_t)(g*4 + rr)*CC + c];
        float agg = 0.f;
        #pragma unroll
        for (int q = 0; q < KNNK; q++) agg += fe[(size_t)nb[rr][q]*CC + c];
        h2[rr][CC + c] = agg * (1.0f/KNNK);
    }
    __syncthreads();

    float acc[4];
    float bv = bias[c];
    #pragma unroll
    for (int rr = 0; rr < 4; rr++) acc[rr] = bv;
    #pragma unroll 4
    for (int r = 0; r < 2*CC; r++) {
        float wv = W[(size_t)r*CC + c];
        #pragma unroll
        for (int rr = 0; rr < 4; rr++) acc[rr] += h2[rr][r]*wv;
    }

    for (int rr = 0; rr < 4; rr++) {
        red[c] = acc[rr]*acc[rr]; __syncthreads();
        for (int off = 64; off > 0; off >>= 1) { if (c < off) red[c] += red[c+off]; __syncthreads(); }
        float inv = rsqrtf(red[0]); __syncthreads();
        fg[(size_t)(g*4 + rr)*CC + c] = acc[rr]*inv;
    }
}

// ---------------- smooth + positive logits -----------------------------------
__device__ __forceinline__ float breduce128(float v, float* red, int c)
{
    red[c] = v; __syncthreads();
    for (int off = 64; off > 0; off >>= 1) { if (c < off) red[c] += red[c+off]; __syncthreads(); }
    float r = red[0]; __syncthreads();
    return r;
}

__global__ __launch_bounds__(128) void smooth_pos_kernel(const int* __restrict__ idx,
        const float* __restrict__ mem_l, const float* __restrict__ mem_ab)
{
    const int b = blockIdx.x, c = threadIdx.x;
    __shared__ float red[CC];
    const int id = idx[b];
    float ml  = mem_l [(size_t)id*CC + c];
    float mab = mem_ab[(size_t)id*CC + c];
    float fes = g_fes[(size_t)b*CC + c], fet = g_fet[(size_t)b*CC + c];
    float fgs = g_fgs[(size_t)b*CC + c], fgt = g_fgt[(size_t)b*CC + c];

    float sgs = ml *0.75f + fgs*0.25f;
    float sgt = mab*0.75f + fgt*0.25f;
    sgs *= rsqrtf(breduce128(sgs*sgs, red, c));
    sgt *= rsqrtf(breduce128(sgt*sgt, red, c));

    float ls = breduce128(mab*fes, red, c);
    float lt = breduce128(ml *fet, red, c);
    float gs = breduce128(sgt*fgs, red, c);
    float gt = breduce128(sgs*fgt, red, c);
    if (c == 0) {
        g_pos[0*BB+b] = ls; g_pos[1*BB+b] = lt;
        g_pos[2*BB+b] = gs; g_pos[3*BB+b] = gt;
    }
}

// ---------------- heavy kernel: gathered dual-GEMV + fixed-shift LSE ---------
// grid (BB*4, 2): x -> (b, quarter), y -> bank. 256 threads / 8 warps.
// 8 lanes per row, 4 rows per iteration, ping-pong register prefetch so the
// next rows' LDGs are in flight across the shuffle convergence barrier.
__device__ __forceinline__ void neg_dots(const float4* __restrict__ xx,
        const float4* __restrict__ a1, const float4* __restrict__ a2,
        float& d1, float& d2)
{
    d1 = 0.f; d2 = 0.f;
    #pragma unroll
    for (int i = 0; i < 4; i++) {
        d1 += xx[i].x*a1[i].x + xx[i].y*a1[i].y + xx[i].z*a1[i].z + xx[i].w*a1[i].w;
        d2 += xx[i].x*a2[i].x + xx[i].y*a2[i].y + xx[i].z*a2[i].z + xx[i].w*a2[i].w;
    }
}

__global__ __launch_bounds__(256) void neg_kernel(const int* __restrict__ cidx,
        const float* __restrict__ mem_l, const float* __restrict__ mem_ab)
{
    const int b = blockIdx.x >> 2, quarter = blockIdx.x & 3, bank = blockIdx.y;
    const float* mem = bank ? mem_ab : mem_l;
    const float* v1p = (bank ? g_fet : g_fes) + (size_t)b*CC;
    const float* v2p = (bank ? g_fgt : g_fgs) + (size_t)b*CC;
    const int t = threadIdx.x, w = t >> 5, lane = t & 31;
    const int j = lane & 7;     // 16-float segment of the row
    const int r = lane >> 3;    // row within group of 4

    __shared__ int sidx[1024];
    __shared__ float ss1[8], ss2[8];

    const int* gci = cidx + (size_t)b*KK + quarter*1024;
    for (int i = t; i < 1024; i += 256) sidx[i] = gci[i];

    float4 a1[4], a2[4];
    #pragma unroll
    for (int i = 0; i < 4; i++) {
        a1[i] = ((const float4*)v1p)[j + 8*i];
        a2[i] = ((const float4*)v2p)[j + 8*i];
    }
    __syncthreads();

    const int base = w*128;   // this warp's 128 rows: sidx[base + it*4 + r]

    float4 x0[4], x1[4];
    {
        const float4* mp = (const float4*)(mem + (size_t)sidx[base + r]*CC);
        #pragma unroll
        for (int i = 0; i < 4; i++) x0[i] = mp[j + 8*i];
    }
    {
        const float4* mp = (const float4*)(mem + (size_t)sidx[base + 4 + r]*CC);
        #pragma unroll
        for (int i = 0; i < 4; i++) x1[i] = mp[j + 8*i];
    }

    float s1 = 0.f, s2 = 0.f;
    for (int it = 0; it < 32; it += 2) {
        float d1, d2;
        // ---- iteration it (buffer x0) ----
        neg_dots(x0, a1, a2, d1, d2);                 // x0 dead after this
        {   // prefetch rows for it+2 into x0 BEFORE the shuffle chain
            const float4* mp = (const float4*)(mem + (size_t)sidx[base + (((it+2)&31)<<2) + r]*CC);
            #pragma unroll
            for (int i = 0; i < 4; i++) x0[i] = mp[j + 8*i];
        }
        #pragma unroll
        for (int o = 4; o; o >>= 1) {
            d1 += __shfl_xor_sync(0xffffffffu, d1, o);
            d2 += __shfl_xor_sync(0xffffffffu, d2, o);
        }
        s1 += __expf(fmaf(d1, INV_T, -LSE_SHIFT));
        s2 += __expf(fmaf(d2, INV_T, -LSE_SHIFT));

        // ---- iteration it+1 (buffer x1) ----
        neg_dots(x1, a1, a2, d1, d2);
        {   // prefetch rows for it+3 into x1
            const float4* mp = (const float4*)(mem + (size_t)sidx[base + (((it+3)&31)<<2) + r]*CC);
            #pragma unroll
            for (int i = 0; i < 4; i++) x1[i] = mp[j + 8*i];
        }
        #pragma unroll
        for (int o = 4; o; o >>= 1) {
            d1 += __shfl_xor_sync(0xffffffffu, d1, o);
            d2 += __shfl_xor_sync(0xffffffffu, d2, o);
        }
        s1 += __expf(fmaf(d1, INV_T, -LSE_SHIFT));
        s2 += __expf(fmaf(d2, INV_T, -LSE_SHIFT));
    }

    // warp total: each group contributed 8 identical copies -> exact 1/8 scale
    #pragma unroll
    for (int o = 16; o; o >>= 1) {
        s1 += __shfl_xor_sync(0xffffffffu, s1, o);
        s2 += __shfl_xor_sync(0xffffffffu, s2, o);
    }
    if (lane == 0) { ss1[w] = s1 * 0.125f; ss2[w] = s2 * 0.125f; }
    __syncthreads();
    if (t == 0) {
        float S1 = 0.f, S2 = 0.f;
        #pragma unroll
        for (int q = 0; q < 8; q++) { S1 += ss1[q]; S2 += ss2[q]; }
        g_psum[bank][b][quarter]     = S1;
        g_psum[2 + bank][b][quarter] = S2;
    }
}

// ---------------- final reduce -----------------------------------------------
__global__ __launch_bounds__(256) void final_kernel(float* __restrict__ out)
{
    const int t = threadIdx.x;
    __shared__ float red[256];
    float v = 0.f;
    #pragma unroll
    for (int s = 0; s < 4; s++) {
        float p = g_pos[s*BB + t] * INV_T;
        float S = __expf(p - LSE_SHIFT);
        #pragma unroll
        for (int h = 0; h < 4; h++) S += g_psum[s][t][h];
        v += LSE_SHIFT + logf(S) - p;
    }
    red[t] = v; __syncthreads();
    for (int off = 128; off > 0; off >>= 1) { if (t < off) red[t] += red[t+off]; __syncthreads(); }
    if (t == 0) out[0] = red[0] * (1.0f/BB);
}

// ---------------- launch -----------------------------------------------------
extern "C" void kernel_launch(void* const* d_in, const int* in_sizes, int n_in,
                              void* d_out, int out_size)
{
    const float* f_s   = (const float*)d_in[1];
    const float* l_s   = (const float*)d_in[2];
    const float* f_t   = (const float*)d_in[3];
    const float* l_t   = (const float*)d_in[4];
    const int*   idx   = (const int*)  d_in[5];
    const int*   cidx  = (const int*)  d_in[6];
    const float* W_es  = (const float*)d_in[7];
    const float* b_es  = (const float*)d_in[8];
    const float* W_et  = (const float*)d_in[9];
    const float* b_et  = (const float*)d_in[10];
    const float* W_gs  = (const float*)d_in[11];
    const float* b_gs  = (const float*)d_in[12];
    const float* W_gt  = (const float*)d_in[13];
    const float* b_gt  = (const float*)d_in[14];
    const float* mem_l = (const float*)d_in[15];
    const float* mem_ab= (const float*)d_in[16];
    float* out = (float*)d_out;

    embed_kernel<1024, 4><<<BB/4, 256>>>(f_s, W_es, b_es);      // -> g_fes
    embed_kernel<2048, 4><<<BB/4, 256>>>(f_t, W_et, b_et);      // -> g_fet
    soft_kernel<<<dim3(BB, 2), 128>>>(l_s, l_t);                // -> g_u, g_uT
    knn_kernel<<<dim3(BB, 2), 128>>>();                         // -> g_nbr
    gnn_kernel<<<dim3(BB/4, 2), 128>>>(W_gs, b_gs, W_gt, b_gt); // -> g_fgs/g_fgt
    neg_kernel<<<dim3(BB*4, 2), 256>>>(cidx, mem_l, mem_ab);    // -> g_psum
    smooth_pos_kernel<<<BB, 128>>>(idx, mem_l, mem_ab);         // -> g_pos
    final_kernel<<<1, 256>>>(out);
}